// round 14
// baseline (speedup 1.0000x reference)
#include <cuda_runtime.h>
#include <cuda_bf16.h>
#include <math.h>

#define B_   8
#define CIN  128
#define CK   64
#define CV   64
#define CO   128
#define N_   4096
#define KVCHUNKS 32

// ---------------- scratch ----------------
__device__ float g_yq[B_ * CK * N_];              // raw conv(q)+bias (f32, for stats)
__device__ float g_yk[B_ * CK * N_];
__device__ float g_scale[2 * CK];
__device__ float g_shift[2 * CK];
__device__ __nv_bfloat16 g_Wh[2 * 64 * CIN];      // pre-split weights [wsel][co][ci]
__device__ __nv_bfloat16 g_Wl[2 * 64 * CIN];
__device__ __nv_bfloat16 g_qh[B_ * CK * N_], g_ql[B_ * CK * N_];   // normalized q
__device__ __nv_bfloat16 g_kh[B_ * CK * N_], g_kl[B_ * CK * N_];   // normalized k
__device__ __nv_bfloat16 g_vh[B_ * CV * N_], g_vl[B_ * CV * N_];   // conv v
__device__ float g_vsumpart[KVCHUNKS * B_ * CV];
__device__ float g_kvpart[KVCHUNKS * B_ * CK * CV];
__device__ __nv_bfloat16 g_Mh[B_ * CO * CK], g_Ml[B_ * CO * CK];   // M^T pre-split
__device__ float g_obias[B_ * CO];

// ---------------- mma / ldmatrix helpers ----------------
__device__ __forceinline__ unsigned su32(const void* p) {
    return (unsigned)__cvta_generic_to_shared(p);
}
#define LDSM_X4(r, addr) \
    asm volatile("ldmatrix.sync.aligned.m8n8.x4.shared.b16 {%0,%1,%2,%3}, [%4];" \
        : "=r"((r)[0]), "=r"((r)[1]), "=r"((r)[2]), "=r"((r)[3]) : "r"(addr))
#define LDSM_X4T(r, addr) \
    asm volatile("ldmatrix.sync.aligned.m8n8.x4.trans.shared.b16 {%0,%1,%2,%3}, [%4];" \
        : "=r"((r)[0]), "=r"((r)[1]), "=r"((r)[2]), "=r"((r)[3]) : "r"(addr))
#define MMA_BF16(d, a, b0, b1) \
    asm volatile("mma.sync.aligned.m16n8k16.row.col.f32.bf16.bf16.f32 " \
        "{%0,%1,%2,%3}, {%4,%5,%6,%7}, {%8,%9}, {%0,%1,%2,%3};" \
        : "+f"((d)[0]), "+f"((d)[1]), "+f"((d)[2]), "+f"((d)[3]) \
        : "r"((a)[0]), "r"((a)[1]), "r"((a)[2]), "r"((a)[3]), "r"(b0), "r"(b1))

__device__ __forceinline__ unsigned packbf(__nv_bfloat16 lo, __nv_bfloat16 hi) {
    return ((unsigned)__bfloat16_as_ushort(hi) << 16) | __bfloat16_as_ushort(lo);
}
__device__ __forceinline__ void split4(float4 f, uint2 &hi, uint2 &lo) {
    __nv_bfloat16 hx = __float2bfloat16(f.x), hy = __float2bfloat16(f.y);
    __nv_bfloat16 hz = __float2bfloat16(f.z), hw = __float2bfloat16(f.w);
    __nv_bfloat16 lx = __float2bfloat16(f.x - __bfloat162float(hx));
    __nv_bfloat16 ly = __float2bfloat16(f.y - __bfloat162float(hy));
    __nv_bfloat16 lz = __float2bfloat16(f.z - __bfloat162float(hz));
    __nv_bfloat16 lw = __float2bfloat16(f.w - __bfloat162float(hw));
    hi.x = packbf(hx, hy); hi.y = packbf(hz, hw);
    lo.x = packbf(lx, ly); lo.y = packbf(lz, lw);
}
__device__ __forceinline__ void split2(float a, float b, unsigned &hi, unsigned &lo) {
    __nv_bfloat16 ha = __float2bfloat16(a), hb = __float2bfloat16(b);
    __nv_bfloat16 la = __float2bfloat16(a - __bfloat162float(ha));
    __nv_bfloat16 lb = __float2bfloat16(b - __bfloat162float(hb));
    hi = packbf(ha, hb); lo = packbf(la, lb);
}

#define ASTR 72
#define BSTR 72

// ---------------- K0: pre-split weights ----------------
// 16384 floats total (2 x 64 x 128); 16 blocks x 256 thr, 1 float4 each.
__global__ void prep_w_kernel(const float* __restrict__ Wk, const float* __restrict__ Wv) {
    int e = blockIdx.x * 256 + threadIdx.x;     // float4 index 0..4095
    int wsel = e >> 11;                          // 2048 float4 per matrix
    int r4 = (e & 2047) * 4;                     // element offset within matrix
    float4 f = *(const float4*)((wsel ? Wv : Wk) + r4);
    uint2 hi, lo; split4(f, hi, lo);
    *(uint2*)&g_Wh[wsel * 8192 + r4] = hi;
    *(uint2*)&g_Wl[wsel * 8192 + r4] = lo;
}

// ---------------- K1: 1x1 conv via bf16-split MMA (copy-staged A) -----------
__global__ __launch_bounds__(256) void conv_mma_kernel(
    const float* __restrict__ xq, const float* __restrict__ xk,
    const float* __restrict__ xv,
    const float* __restrict__ bk, const float* __restrict__ bv)
{
    int which = blockIdx.z;
    const float* x    = (which == 0) ? xq : (which == 1) ? xk : xv;
    const float* bias = (which == 2) ? bv : bk;
    int wsel = (which == 2) ? 1 : 0;
    const __nv_bfloat16* WhP = &g_Wh[wsel * 8192];
    const __nv_bfloat16* WlP = &g_Wl[wsel * 8192];

    int bb = blockIdx.y;
    int n0 = blockIdx.x * 64;
    int tid = threadIdx.x;
    int lane = tid & 31, w = tid >> 5;
    int ct = (w & 3) * 16;
    int ng = (w >> 2) * 32;

    __shared__ __align__(16) __nv_bfloat16 Ah[64 * ASTR];
    __shared__ __align__(16) __nv_bfloat16 Al[64 * ASTR];
    __shared__ __align__(16) __nv_bfloat16 Bh[64 * BSTR];
    __shared__ __align__(16) __nv_bfloat16 Bl[64 * BSTR];

    int q = lane >> 3, rr = lane & 7;
    unsigned aOffH, aOffL, bOffH0, bOffL0, bOffH1, bOffL1;
    {
        int arow = ct + (q & 1) * 8 + rr;
        int acol = (q >> 1) * 8;
        aOffH = su32(Ah) + arow * (ASTR * 2) + acol * 2;
        aOffL = su32(Al) + arow * (ASTR * 2) + acol * 2;
        int brow = (q & 1) * 8 + rr;
        int bcol0 = ng + (q >> 1) * 8;
        int bcol1 = ng + 16 + (q >> 1) * 8;
        bOffH0 = su32(Bh) + brow * (BSTR * 2) + bcol0 * 2;
        bOffL0 = su32(Bl) + brow * (BSTR * 2) + bcol0 * 2;
        bOffH1 = su32(Bh) + brow * (BSTR * 2) + bcol1 * 2;
        bOffL1 = su32(Bl) + brow * (BSTR * 2) + bcol1 * 2;
    }

    int xci = tid >> 4, xnn4 = (tid & 15) * 4;
    const float* xbase = &x[((size_t)(bb * CIN + xci)) * N_ + n0 + xnn4];
    int wrow = tid >> 3, wc8 = (tid & 7) * 8;    // W copy coords (2 uint4/thread/array)

    float acc[4][4] = {};
    float4 xreg[4];
    #pragma unroll
    for (int i = 0; i < 4; i++)
        xreg[i] = *(const float4*)(xbase + (size_t)(i * 16) * N_);

    for (int s = 0; s < 2; s++) {
        // A staging: pure uint4 copy of pre-split W
        #pragma unroll
        for (int i = 0; i < 2; i++) {
            int row = wrow + i * 32;
            *(uint4*)&Ah[row * ASTR + wc8] = *(const uint4*)&WhP[row * CIN + s * 64 + wc8];
            *(uint4*)&Al[row * ASTR + wc8] = *(const uint4*)&WlP[row * CIN + s * 64 + wc8];
        }
        // B staging: split x from registers
        #pragma unroll
        for (int i = 0; i < 4; i++) {
            int ci = xci + i * 16;
            uint2 hi, lo; split4(xreg[i], hi, lo);
            *(uint2*)&Bh[ci * BSTR + xnn4] = hi;
            *(uint2*)&Bl[ci * BSTR + xnn4] = lo;
        }
        __syncthreads();

        if (s == 0) {
            #pragma unroll
            for (int i = 0; i < 4; i++)
                xreg[i] = *(const float4*)(xbase + (size_t)(64 + i * 16) * N_);
        }

        #pragma unroll
        for (int ks = 0; ks < 4; ks++) {
            unsigned aStep = ks * 32;
            unsigned bStep = ks * 16 * (BSTR * 2);
            unsigned ah[4], al[4], bh[4], bl[4], bh2[4], bl2[4];
            LDSM_X4(ah, aOffH + aStep);
            LDSM_X4(al, aOffL + aStep);
            LDSM_X4T(bh, bOffH0 + bStep);
            LDSM_X4T(bl, bOffL0 + bStep);
            LDSM_X4T(bh2, bOffH1 + bStep);
            LDSM_X4T(bl2, bOffL1 + bStep);
            MMA_BF16(acc[0], ah, bh[0], bh[1]);
            MMA_BF16(acc[0], ah, bl[0], bl[1]);
            MMA_BF16(acc[0], al, bh[0], bh[1]);
            MMA_BF16(acc[1], ah, bh[2], bh[3]);
            MMA_BF16(acc[1], ah, bl[2], bl[3]);
            MMA_BF16(acc[1], al, bh[2], bh[3]);
            MMA_BF16(acc[2], ah, bh2[0], bh2[1]);
            MMA_BF16(acc[2], ah, bl2[0], bl2[1]);
            MMA_BF16(acc[2], al, bh2[0], bh2[1]);
            MMA_BF16(acc[3], ah, bh2[2], bh2[3]);
            MMA_BF16(acc[3], ah, bl2[2], bl2[3]);
            MMA_BF16(acc[3], al, bh2[2], bh2[3]);
        }
        __syncthreads();
    }

    int r4 = lane >> 2, c2 = (lane & 3) * 2;
    int row0 = ct + r4, row1 = ct + r4 + 8;
    float b0v = bias[row0], b1v = bias[row1];
    if (which == 2) {
        // v: write pre-split bf16 hi/lo
        #pragma unroll
        for (int t = 0; t < 4; t++) {
            int col = n0 + ng + t * 8 + c2;
            size_t off0 = ((size_t)(bb * 64 + row0)) * N_ + col;
            size_t off1 = ((size_t)(bb * 64 + row1)) * N_ + col;
            unsigned h, l;
            split2(acc[t][0] + b0v, acc[t][1] + b0v, h, l);
            *(unsigned*)&g_vh[off0] = h; *(unsigned*)&g_vl[off0] = l;
            split2(acc[t][2] + b1v, acc[t][3] + b1v, h, l);
            *(unsigned*)&g_vh[off1] = h; *(unsigned*)&g_vl[off1] = l;
        }
    } else {
        float* y = which ? g_yk : g_yq;
        #pragma unroll
        for (int t = 0; t < 4; t++) {
            int col = n0 + ng + t * 8 + c2;
            *(float2*)&y[((size_t)(bb * 64 + row0)) * N_ + col] =
                make_float2(acc[t][0] + b0v, acc[t][1] + b0v);
            *(float2*)&y[((size_t)(bb * 64 + row1)) * N_ + col] =
                make_float2(acc[t][2] + b1v, acc[t][3] + b1v);
        }
    }
}

// ---------------- K2: BN batch stats ----------------
__global__ __launch_bounds__(256) void bn_stats_kernel(
    const float* __restrict__ gamma, const float* __restrict__ beta)
{
    int c = blockIdx.x & 63;
    int which = blockIdx.x >> 6;
    const float* y = which ? g_yk : g_yq;
    int tid = threadIdx.x;

    float s = 0.f, ss = 0.f;
    #pragma unroll
    for (int b = 0; b < B_; b++) {
        const float4* row = (const float4*)(y + ((size_t)(b * 64 + c)) * N_);
        #pragma unroll
        for (int i = 0; i < 4; i++) {
            float4 f = row[tid + i * 256];
            s  += f.x + f.y + f.z + f.w;
            ss += f.x * f.x + f.y * f.y + f.z * f.z + f.w * f.w;
        }
    }
    #pragma unroll
    for (int o = 16; o; o >>= 1) {
        s  += __shfl_down_sync(0xffffffffu, s, o);
        ss += __shfl_down_sync(0xffffffffu, ss, o);
    }
    __shared__ float rs[8], rss[8];
    int wid = tid >> 5, lane = tid & 31;
    if (lane == 0) { rs[wid] = s; rss[wid] = ss; }
    __syncthreads();
    if (tid == 0) {
        float S = 0.f, SS = 0.f;
        #pragma unroll
        for (int i = 0; i < 8; i++) { S += rs[i]; SS += rss[i]; }
        const float inv = 1.0f / 32768.0f;
        float mean = S * inv;
        float var  = SS * inv - mean * mean;
        float sc = gamma[c] * rsqrtf(var + 1e-5f);
        g_scale[blockIdx.x] = sc;
        g_shift[blockIdx.x] = beta[c] - mean * sc;
    }
}

// ---------------- K3: BN + L2-normalize -> write bf16 hi/lo planes -----------
__global__ __launch_bounds__(512) void norm_kernel() {
    int blk = blockIdx.x;
    int which = blk >> 7;
    int r = blk & 127;
    int b = r >> 4;
    int n0 = (r & 15) * 256;
    const float* y = which ? g_yk : g_yq;
    __nv_bfloat16* gh = which ? g_kh : g_qh;
    __nv_bfloat16* gl = which ? g_kl : g_ql;
    int tid = threadIdx.x;
    int qt = tid >> 7;
    int l = tid & 127;
    int n = n0 + l * 2;

    __shared__ float scs[64], shs[64];
    __shared__ float ss4[4][256];
    if (tid < 64) {
        scs[tid] = g_scale[which * 64 + tid];
        shs[tid] = g_shift[which * 64 + tid];
    }
    __syncthreads();

    float2 v[16];
    float ssa = 0.f, ssb = 0.f;
    #pragma unroll
    for (int i = 0; i < 16; i++) {
        int c = qt * 16 + i;
        float2 t = *(const float2*)&y[((size_t)(b * 64 + c)) * N_ + n];
        t.x = t.x * scs[c] + shs[c];
        t.y = t.y * scs[c] + shs[c];
        v[i] = t;
        ssa += t.x * t.x;  ssb += t.y * t.y;
    }
    ss4[qt][l * 2] = ssa;  ss4[qt][l * 2 + 1] = ssb;
    __syncthreads();
    float rna = 1.0f / (sqrtf(ss4[0][l*2]   + ss4[1][l*2]   + ss4[2][l*2]   + ss4[3][l*2])   + 1e-7f);
    float rnb = 1.0f / (sqrtf(ss4[0][l*2+1] + ss4[1][l*2+1] + ss4[2][l*2+1] + ss4[3][l*2+1]) + 1e-7f);
    #pragma unroll
    for (int i = 0; i < 16; i++) {
        int c = qt * 16 + i;
        size_t off = ((size_t)(b * 64 + c)) * N_ + n;
        unsigned h, lo2; split2(v[i].x * rna, v[i].y * rnb, h, lo2);
        *(unsigned*)&gh[off] = h;
        *(unsigned*)&gl[off] = lo2;
    }
}

// ---------------- K4: KV via bf16 MMA (pure-copy staging + prefetch) ---------
__global__ __launch_bounds__(256) void kv_mma_kernel() {
    int chunk = blockIdx.x, b = blockIdx.y;
    int tid = threadIdx.x;
    int lane = tid & 31, w = tid >> 5;
    int ct = (w & 3) * 16;
    int cg = (w >> 2) * 32;

    __shared__ __align__(16) __nv_bfloat16 Kh[64 * ASTR];
    __shared__ __align__(16) __nv_bfloat16 Kl[64 * ASTR];
    __shared__ __align__(16) __nv_bfloat16 Vh[64 * ASTR];
    __shared__ __align__(16) __nv_bfloat16 Vl[64 * ASTR];
    __shared__ float vps[64][4];

    int q = lane >> 3, rr = lane & 7;
    unsigned aH, aL, bH0, bL0, bH1, bL1;
    {
        int arow = ct + (q & 1) * 8 + rr;
        int acol = (q >> 1) * 8;
        aH = su32(Kh) + arow * (ASTR * 2) + acol * 2;
        aL = su32(Kl) + arow * (ASTR * 2) + acol * 2;
        int brow = cg + (q >> 1) * 8 + rr;
        int bcol = (q & 1) * 8;
        bH0 = su32(Vh) + brow * (ASTR * 2) + bcol * 2;
        bL0 = su32(Vl) + brow * (ASTR * 2) + bcol * 2;
        bH1 = bH0 + 16 * (ASTR * 2);
        bL1 = bL0 + 16 * (ASTR * 2);
    }

    int cc = tid & 63, q4 = tid >> 6;
    int er = tid >> 3, ec8 = (tid & 7) * 8;   // copy coords: 2 uint4/thread/array
    float acc[4][4] = {};
    float vp = 0.f;

    uint4 rkh[2], rkl[2], rvh[2], rvl[2];
    // preload tile 0
    #pragma unroll
    for (int i = 0; i < 2; i++) {
        size_t off = ((size_t)(b * 64 + er + i * 32)) * N_ + chunk * 128 + ec8;
        rkh[i] = *(const uint4*)&g_kh[off];
        rkl[i] = *(const uint4*)&g_kl[off];
        rvh[i] = *(const uint4*)&g_vh[off];
        rvl[i] = *(const uint4*)&g_vl[off];
    }

    for (int t = 0; t < 2; t++) {
        #pragma unroll
        for (int i = 0; i < 2; i++) {
            int row = er + i * 32;
            *(uint4*)&Kh[row * ASTR + ec8] = rkh[i];
            *(uint4*)&Kl[row * ASTR + ec8] = rkl[i];
            *(uint4*)&Vh[row * ASTR + ec8] = rvh[i];
            *(uint4*)&Vl[row * ASTR + ec8] = rvl[i];
        }
        __syncthreads();

        if (t == 0) {
            #pragma unroll
            for (int i = 0; i < 2; i++) {
                size_t off = ((size_t)(b * 64 + er + i * 32)) * N_ + chunk * 128 + 64 + ec8;
                rkh[i] = *(const uint4*)&g_kh[off];
                rkl[i] = *(const uint4*)&g_kl[off];
                rvh[i] = *(const uint4*)&g_vh[off];
                rvl[i] = *(const uint4*)&g_vl[off];
            }
        }

        #pragma unroll
        for (int ks = 0; ks < 4; ks++) {
            unsigned step = ks * 32;
            unsigned ah[4], al[4], bh[4], bl[4], bh2[4], bl2[4];
            LDSM_X4(ah, aH + step);
            LDSM_X4(al, aL + step);
            LDSM_X4(bh, bH0 + step);
            LDSM_X4(bl, bL0 + step);
            LDSM_X4(bh2, bH1 + step);
            LDSM_X4(bl2, bL1 + step);
            MMA_BF16(acc[0], ah, bh[0], bh[1]);
            MMA_BF16(acc[0], ah, bl[0], bl[1]);
            MMA_BF16(acc[0], al, bh[0], bh[1]);
            MMA_BF16(acc[1], ah, bh[2], bh[3]);
            MMA_BF16(acc[1], ah, bl[2], bl[3]);
            MMA_BF16(acc[1], al, bh[2], bh[3]);
            MMA_BF16(acc[2], ah, bh2[0], bh2[1]);
            MMA_BF16(acc[2], ah, bl2[0], bl2[1]);
            MMA_BF16(acc[2], al, bh2[0], bh2[1]);
            MMA_BF16(acc[3], ah, bh2[2], bh2[3]);
            MMA_BF16(acc[3], ah, bl2[2], bl2[3]);
            MMA_BF16(acc[3], al, bh2[2], bh2[3]);
        }
        // fused V row sums (hi+lo) from smem bf16
        #pragma unroll
        for (int i = 0; i < 16; i++) {
            int idx = cc * ASTR + q4 * 16 + i;
            vp += __bfloat162float(Vh[idx]) + __bfloat162float(Vl[idx]);
        }
        __syncthreads();
    }

    int r4 = lane >> 2, c2 = (lane & 3) * 2;
    int row0 = ct + r4, row1 = ct + r4 + 8;
    float* base = &g_kvpart[(((size_t)chunk * B_ + b)) * 4096];
    #pragma unroll
    for (int t = 0; t < 4; t++) {
        int col = cg + t * 8 + c2;
        *(float2*)&base[row0 * 64 + col] = make_float2(acc[t][0], acc[t][1]);
        *(float2*)&base[row1 * 64 + col] = make_float2(acc[t][2], acc[t][3]);
    }

    vps[cc][q4] = vp;
    __syncthreads();
    if (tid < 64)
        g_vsumpart[((size_t)chunk * B_ + b) * 64 + tid] =
            vps[tid][0] + vps[tid][1] + vps[tid][2] + vps[tid][3];
}

// ---------------- K5: M^T -> bf16 hi/lo; obias --------------------------------
__global__ __launch_bounds__(256) void m_kernel(
    const float* __restrict__ Ww, const float* __restrict__ bw)
{
    int b = blockIdx.x;
    __shared__ float KVs[64][64];
    __shared__ float WwT[64][128];
    __shared__ float vs_s[64];
    int tid = threadIdx.x;

    if (tid < 64) {
        float S = 0.f;
        #pragma unroll
        for (int c2 = 0; c2 < KVCHUNKS; c2++)
            S += g_vsumpart[((size_t)c2 * B_ + b) * 64 + tid];
        vs_s[tid] = S;
    }
    for (int e = tid; e < 4096; e += 256) {
        float s = 0.f;
        #pragma unroll
        for (int c2 = 0; c2 < KVCHUNKS; c2++)
            s += g_kvpart[((size_t)c2 * B_ + b) * 4096 + e];
        KVs[e >> 6][e & 63] = s;
    }
    for (int e = tid; e < 8192; e += 256) {
        int cv = e >> 7, co = e & 127;
        WwT[cv][co] = Ww[co * CV + cv];
    }
    __syncthreads();

    int co = tid & 127;
    for (int ck = (tid >> 7); ck < 64; ck += 2) {
        float s = 0.f;
        #pragma unroll 8
        for (int cv = 0; cv < 64; cv++) s += KVs[ck][cv] * WwT[cv][co];
        size_t idx = ((size_t)b * 128 + co) * 64 + ck;
        __nv_bfloat16 h = __float2bfloat16(s);
        g_Mh[idx] = h;
        g_Ml[idx] = __float2bfloat16(s - __bfloat162float(h));
    }
    if (tid < 128) {
        float s = bw[tid];
        #pragma unroll 8
        for (int cv = 0; cv < 64; cv++) s += vs_s[cv] * WwT[cv][tid];
        g_obias[b * CO + tid] = s;
    }
}

// ---------------- K6: out via bf16 MMA (pure-copy staging) -------------------
__global__ __launch_bounds__(256) void out_mma_kernel(float* __restrict__ out) {
    int b = blockIdx.y, n0 = blockIdx.x * 64, ch = blockIdx.z;
    int co0 = ch * 64;
    int tid = threadIdx.x;
    int lane = tid & 31, w = tid >> 5;
    int ct = (w & 3) * 16;
    int ng = (w >> 2) * 32;

    __shared__ __align__(16) __nv_bfloat16 Ah[64 * ASTR];
    __shared__ __align__(16) __nv_bfloat16 Al[64 * ASTR];
    __shared__ __align__(16) __nv_bfloat16 Bh[64 * BSTR];
    __shared__ __align__(16) __nv_bfloat16 Bl[64 * BSTR];

    int q = lane >> 3, rr = lane & 7;
    unsigned aOffH, aOffL, bOffH0, bOffL0, bOffH1, bOffL1;
    {
        int arow = ct + (q & 1) * 8 + rr;
        int acol = (q >> 1) * 8;
        aOffH = su32(Ah) + arow * (ASTR * 2) + acol * 2;
        aOffL = su32(Al) + arow * (ASTR * 2) + acol * 2;
        int brow = (q & 1) * 8 + rr;
        int bcol0 = ng + (q >> 1) * 8;
        int bcol1 = ng + 16 + (q >> 1) * 8;
        bOffH0 = su32(Bh) + brow * (BSTR * 2) + bcol0 * 2;
        bOffL0 = su32(Bl) + brow * (BSTR * 2) + bcol0 * 2;
        bOffH1 = su32(Bh) + brow * (BSTR * 2) + bcol1 * 2;
        bOffL1 = su32(Bl) + brow * (BSTR * 2) + bcol1 * 2;
    }

    int er = tid >> 3, ec8 = (tid & 7) * 8;
    // A staging: pure copy from pre-split M^T
    #pragma unroll
    for (int i = 0; i < 2; i++) {
        int row = er + i * 32;
        size_t off = ((size_t)(b * 128 + co0 + row)) * 64 + ec8;
        *(uint4*)&Ah[row * ASTR + ec8] = *(const uint4*)&g_Mh[off];
        *(uint4*)&Al[row * ASTR + ec8] = *(const uint4*)&g_Ml[off];
    }
    // B staging: pure copy from pre-split normalized q
    #pragma unroll
    for (int i = 0; i < 2; i++) {
        int row = er + i * 32;
        size_t off = ((size_t)(b * 64 + row)) * N_ + n0 + ec8;
        *(uint4*)&Bh[row * BSTR + ec8] = *(const uint4*)&g_qh[off];
        *(uint4*)&Bl[row * BSTR + ec8] = *(const uint4*)&g_ql[off];
    }
    __syncthreads();

    float acc[4][4] = {};
    #pragma unroll
    for (int ks = 0; ks < 4; ks++) {
        unsigned aStep = ks * 32;
        unsigned bStep = ks * 16 * (BSTR * 2);
        unsigned ah[4], al[4], bh[4], bl[4], bh2[4], bl2[4];
        LDSM_X4(ah, aOffH + aStep);
        LDSM_X4(al, aOffL + aStep);
        LDSM_X4T(bh, bOffH0 + bStep);
        LDSM_X4T(bl, bOffL0 + bStep);
        LDSM_X4T(bh2, bOffH1 + bStep);
        LDSM_X4T(bl2, bOffL1 + bStep);
        MMA_BF16(acc[0], ah, bh[0], bh[1]);
        MMA_BF16(acc[0], ah, bl[0], bl[1]);
        MMA_BF16(acc[0], al, bh[0], bh[1]);
        MMA_BF16(acc[1], ah, bh[2], bh[3]);
        MMA_BF16(acc[1], ah, bl[2], bl[3]);
        MMA_BF16(acc[1], al, bh[2], bh[3]);
        MMA_BF16(acc[2], ah, bh2[0], bh2[1]);
        MMA_BF16(acc[2], ah, bl2[0], bl2[1]);
        MMA_BF16(acc[2], al, bh2[0], bh2[1]);
        MMA_BF16(acc[3], ah, bh2[2], bh2[3]);
        MMA_BF16(acc[3], ah, bl2[2], bl2[3]);
        MMA_BF16(acc[3], al, bh2[2], bh2[3]);
    }

    int r4 = lane >> 2, c2 = (lane & 3) * 2;
    int row0 = co0 + ct + r4, row1 = row0 + 8;
    float b0v = g_obias[b * CO + row0], b1v = g_obias[b * CO + row1];
    #pragma unroll
    for (int t = 0; t < 4; t++) {
        int col = n0 + ng + t * 8 + c2;
        *(float2*)&out[((size_t)(b * CO + row0)) * N_ + col] =
            make_float2(acc[t][0] + b0v, acc[t][1] + b0v);
        *(float2*)&out[((size_t)(b * CO + row1)) * N_ + col] =
            make_float2(acc[t][2] + b1v, acc[t][3] + b1v);
    }
}

// ---------------- launch ----------------
extern "C" void kernel_launch(void* const* d_in, const int* in_sizes, int n_in,
                              void* d_out, int out_size) {
    const float* q     = (const float*)d_in[0];
    const float* k     = (const float*)d_in[1];
    const float* v     = (const float*)d_in[2];
    const float* Wk    = (const float*)d_in[3];
    const float* bk    = (const float*)d_in[4];
    const float* gamma = (const float*)d_in[5];
    const float* beta  = (const float*)d_in[6];
    const float* Wv    = (const float*)d_in[7];
    const float* bv    = (const float*)d_in[8];
    const float* Ww    = (const float*)d_in[9];
    const float* bw    = (const float*)d_in[10];
    float* out = (float*)d_out;

    prep_w_kernel<<<16, 256>>>(Wk, Wv);
    conv_mma_kernel<<<dim3(64, B_, 3), 256>>>(q, k, v, bk, bv);
    bn_stats_kernel<<<128, 256>>>(gamma, beta);
    norm_kernel<<<256, 512>>>();
    kv_mma_kernel<<<dim3(KVCHUNKS, B_), 256>>>();
    m_kernel<<<B_, 256>>>(Ww, bw);
    out_mma_kernel<<<dim3(64, B_, 2), 256>>>(out);
}

// round 15
// speedup vs baseline: 1.1638x; 1.1638x over previous
#include <cuda_runtime.h>
#include <cuda_bf16.h>
#include <math.h>

#define B_   8
#define CIN  128
#define CK   64
#define CV   64
#define CO   128
#define N_   4096
#define KVCHUNKS 32

// ---------------- scratch ----------------
__device__ float g_yq[B_ * CK * N_];
__device__ float g_yk[B_ * CK * N_];
__device__ float g_yv[B_ * CV * N_];
__device__ float g_scale[2 * CK];
__device__ float g_shift[2 * CK];
__device__ __nv_bfloat16 g_Wh[2 * 64 * CIN];   // pre-split weights [wsel][co][ci]
__device__ __nv_bfloat16 g_Wl[2 * 64 * CIN];
__device__ float g_vsumpart[KVCHUNKS * B_ * CV];
__device__ float g_kvpart[KVCHUNKS * B_ * CK * CV];
__device__ float g_M[B_ * CO * CK];      // TRANSPOSED: [b][co][ck]
__device__ float g_obias[B_ * CO];

// ---------------- mma / ldmatrix helpers ----------------
__device__ __forceinline__ unsigned su32(const void* p) {
    return (unsigned)__cvta_generic_to_shared(p);
}
#define LDSM_X4(r, addr) \
    asm volatile("ldmatrix.sync.aligned.m8n8.x4.shared.b16 {%0,%1,%2,%3}, [%4];" \
        : "=r"((r)[0]), "=r"((r)[1]), "=r"((r)[2]), "=r"((r)[3]) : "r"(addr))
#define LDSM_X4T(r, addr) \
    asm volatile("ldmatrix.sync.aligned.m8n8.x4.trans.shared.b16 {%0,%1,%2,%3}, [%4];" \
        : "=r"((r)[0]), "=r"((r)[1]), "=r"((r)[2]), "=r"((r)[3]) : "r"(addr))
#define MMA_BF16(d, a, b0, b1) \
    asm volatile("mma.sync.aligned.m16n8k16.row.col.f32.bf16.bf16.f32 " \
        "{%0,%1,%2,%3}, {%4,%5,%6,%7}, {%8,%9}, {%0,%1,%2,%3};" \
        : "+f"((d)[0]), "+f"((d)[1]), "+f"((d)[2]), "+f"((d)[3]) \
        : "r"((a)[0]), "r"((a)[1]), "r"((a)[2]), "r"((a)[3]), "r"(b0), "r"(b1))

__device__ __forceinline__ unsigned packbf(__nv_bfloat16 lo, __nv_bfloat16 hi) {
    return ((unsigned)__bfloat16_as_ushort(hi) << 16) | __bfloat16_as_ushort(lo);
}
__device__ __forceinline__ void split4(float4 f, uint2 &hi, uint2 &lo) {
    __nv_bfloat16 hx = __float2bfloat16(f.x), hy = __float2bfloat16(f.y);
    __nv_bfloat16 hz = __float2bfloat16(f.z), hw = __float2bfloat16(f.w);
    __nv_bfloat16 lx = __float2bfloat16(f.x - __bfloat162float(hx));
    __nv_bfloat16 ly = __float2bfloat16(f.y - __bfloat162float(hy));
    __nv_bfloat16 lz = __float2bfloat16(f.z - __bfloat162float(hz));
    __nv_bfloat16 lw = __float2bfloat16(f.w - __bfloat162float(hw));
    hi.x = packbf(hx, hy); hi.y = packbf(hz, hw);
    lo.x = packbf(lx, ly); lo.y = packbf(lz, lw);
}

#define ASTR 72
#define BSTR 72

// ---------------- K0: pre-split weights (16 blocks x 256) --------------------
__global__ void prep_w_kernel(const float* __restrict__ Wk, const float* __restrict__ Wv) {
    int e = blockIdx.x * 256 + threadIdx.x;     // float4 index 0..4095
    int wsel = e >> 11;
    int r4 = (e & 2047) * 4;
    float4 f = *(const float4*)((wsel ? Wv : Wk) + r4);
    uint2 hi, lo; split4(f, hi, lo);
    *(uint2*)&g_Wh[wsel * 8192 + r4] = hi;
    *(uint2*)&g_Wl[wsel * 8192 + r4] = lo;
}

// ---------------- K1: conv via bf16-split MMA (copy-staged A, reg prefetch) --
__global__ __launch_bounds__(256) void conv_mma_kernel(
    const float* __restrict__ xq, const float* __restrict__ xk,
    const float* __restrict__ xv,
    const float* __restrict__ bk, const float* __restrict__ bv)
{
    int which = blockIdx.z;
    const float* x    = (which == 0) ? xq : (which == 1) ? xk : xv;
    const float* bias = (which == 2) ? bv : bk;
    int wsel = (which == 2) ? 1 : 0;
    const __nv_bfloat16* WhP = &g_Wh[wsel * 8192];
    const __nv_bfloat16* WlP = &g_Wl[wsel * 8192];
    float* y          = (which == 0) ? g_yq : (which == 1) ? g_yk : g_yv;

    int bb = blockIdx.y;
    int n0 = blockIdx.x * 64;
    int tid = threadIdx.x;
    int lane = tid & 31, w = tid >> 5;
    int ct = (w & 3) * 16;
    int ng = (w >> 2) * 32;

    __shared__ __align__(16) __nv_bfloat16 Ah[64 * ASTR];
    __shared__ __align__(16) __nv_bfloat16 Al[64 * ASTR];
    __shared__ __align__(16) __nv_bfloat16 Bh[64 * BSTR];
    __shared__ __align__(16) __nv_bfloat16 Bl[64 * BSTR];

    int q = lane >> 3, rr = lane & 7;
    unsigned aOffH, aOffL, bOffH0, bOffL0, bOffH1, bOffL1;
    {
        int arow = ct + (q & 1) * 8 + rr;
        int acol = (q >> 1) * 8;
        aOffH = su32(Ah) + arow * (ASTR * 2) + acol * 2;
        aOffL = su32(Al) + arow * (ASTR * 2) + acol * 2;
        int brow = (q & 1) * 8 + rr;
        int bcol0 = ng + (q >> 1) * 8;
        int bcol1 = ng + 16 + (q >> 1) * 8;
        bOffH0 = su32(Bh) + brow * (BSTR * 2) + bcol0 * 2;
        bOffL0 = su32(Bl) + brow * (BSTR * 2) + bcol0 * 2;
        bOffH1 = su32(Bh) + brow * (BSTR * 2) + bcol1 * 2;
        bOffL1 = su32(Bl) + brow * (BSTR * 2) + bcol1 * 2;
    }

    int xci = tid >> 4, xnn4 = (tid & 15) * 4;
    const float* xbase = &x[((size_t)(bb * CIN + xci)) * N_ + n0 + xnn4];
    int wrow = tid >> 3, wc8 = (tid & 7) * 8;    // W copy coords

    float acc[4][4] = {};
    float4 xreg[4];
    #pragma unroll
    for (int i = 0; i < 4; i++)
        xreg[i] = *(const float4*)(xbase + (size_t)(i * 16) * N_);

    for (int s = 0; s < 2; s++) {
        // A staging: pure uint4 copy of pre-split W
        #pragma unroll
        for (int i = 0; i < 2; i++) {
            int row = wrow + i * 32;
            *(uint4*)&Ah[row * ASTR + wc8] = *(const uint4*)&WhP[row * CIN + s * 64 + wc8];
            *(uint4*)&Al[row * ASTR + wc8] = *(const uint4*)&WlP[row * CIN + s * 64 + wc8];
        }
        // B staging: split x from prefetched registers
        #pragma unroll
        for (int i = 0; i < 4; i++) {
            int ci = xci + i * 16;
            uint2 hi, lo; split4(xreg[i], hi, lo);
            *(uint2*)&Bh[ci * BSTR + xnn4] = hi;
            *(uint2*)&Bl[ci * BSTR + xnn4] = lo;
        }
        __syncthreads();

        if (s == 0) {
            #pragma unroll
            for (int i = 0; i < 4; i++)
                xreg[i] = *(const float4*)(xbase + (size_t)(64 + i * 16) * N_);
        }

        #pragma unroll
        for (int ks = 0; ks < 4; ks++) {
            unsigned aStep = ks * 32;
            unsigned bStep = ks * 16 * (BSTR * 2);
            unsigned ah[4], al[4], bh[4], bl[4], bh2[4], bl2[4];
            LDSM_X4(ah, aOffH + aStep);
            LDSM_X4(al, aOffL + aStep);
            LDSM_X4T(bh, bOffH0 + bStep);
            LDSM_X4T(bl, bOffL0 + bStep);
            LDSM_X4T(bh2, bOffH1 + bStep);
            LDSM_X4T(bl2, bOffL1 + bStep);
            MMA_BF16(acc[0], ah, bh[0], bh[1]);
            MMA_BF16(acc[0], ah, bl[0], bl[1]);
            MMA_BF16(acc[0], al, bh[0], bh[1]);
            MMA_BF16(acc[1], ah, bh[2], bh[3]);
            MMA_BF16(acc[1], ah, bl[2], bl[3]);
            MMA_BF16(acc[1], al, bh[2], bh[3]);
            MMA_BF16(acc[2], ah, bh2[0], bh2[1]);
            MMA_BF16(acc[2], ah, bl2[0], bl2[1]);
            MMA_BF16(acc[2], al, bh2[0], bh2[1]);
            MMA_BF16(acc[3], ah, bh2[2], bh2[3]);
            MMA_BF16(acc[3], ah, bl2[2], bl2[3]);
            MMA_BF16(acc[3], al, bh2[2], bh2[3]);
        }
        __syncthreads();
    }

    int r4 = lane >> 2, c2 = (lane & 3) * 2;
    int row0 = ct + r4, row1 = ct + r4 + 8;
    float b0v = bias[row0], b1v = bias[row1];
    #pragma unroll
    for (int t = 0; t < 4; t++) {
        int col = n0 + ng + t * 8 + c2;
        *(float2*)&y[((size_t)(bb * 64 + row0)) * N_ + col] =
            make_float2(acc[t][0] + b0v, acc[t][1] + b0v);
        *(float2*)&y[((size_t)(bb * 64 + row1)) * N_ + col] =
            make_float2(acc[t][2] + b1v, acc[t][3] + b1v);
    }
}

// ---------------- K2: BN batch stats (R13, unchanged) ----------------
__global__ __launch_bounds__(256) void bn_stats_kernel(
    const float* __restrict__ gamma, const float* __restrict__ beta)
{
    int c = blockIdx.x & 63;
    int which = blockIdx.x >> 6;
    const float* y = which ? g_yk : g_yq;
    int tid = threadIdx.x;

    float s = 0.f, ss = 0.f;
    #pragma unroll
    for (int b = 0; b < B_; b++) {
        const float4* row = (const float4*)(y + ((size_t)(b * 64 + c)) * N_);
        #pragma unroll
        for (int i = 0; i < 4; i++) {
            float4 f = row[tid + i * 256];
            s  += f.x + f.y + f.z + f.w;
            ss += f.x * f.x + f.y * f.y + f.z * f.z + f.w * f.w;
        }
    }
    #pragma unroll
    for (int o = 16; o; o >>= 1) {
        s  += __shfl_down_sync(0xffffffffu, s, o);
        ss += __shfl_down_sync(0xffffffffu, ss, o);
    }
    __shared__ float rs[8], rss[8];
    int wid = tid >> 5, lane = tid & 31;
    if (lane == 0) { rs[wid] = s; rss[wid] = ss; }
    __syncthreads();
    if (tid == 0) {
        float S = 0.f, SS = 0.f;
        #pragma unroll
        for (int i = 0; i < 8; i++) { S += rs[i]; SS += rss[i]; }
        const float inv = 1.0f / 32768.0f;
        float mean = S * inv;
        float var  = SS * inv - mean * mean;
        float sc = gamma[c] * rsqrtf(var + 1e-5f);
        g_scale[blockIdx.x] = sc;
        g_shift[blockIdx.x] = beta[c] - mean * sc;
    }
}

// ---------------- K3: apply BN + L2-normalize (R13, unchanged) ---------------
__global__ __launch_bounds__(512) void norm_kernel() {
    int blk = blockIdx.x;
    int which = blk >> 7;
    int r = blk & 127;
    int b = r >> 4;
    int n0 = (r & 15) * 256;
    float* y = which ? g_yk : g_yq;
    int tid = threadIdx.x;
    int qt = tid >> 7;
    int l = tid & 127;
    int n = n0 + l * 2;

    __shared__ float scs[64], shs[64];
    __shared__ float ss4[4][256];
    if (tid < 64) {
        scs[tid] = g_scale[which * 64 + tid];
        shs[tid] = g_shift[which * 64 + tid];
    }
    __syncthreads();

    float2 v[16];
    float ssa = 0.f, ssb = 0.f;
    #pragma unroll
    for (int i = 0; i < 16; i++) {
        int c = qt * 16 + i;
        float2 t = *(const float2*)&y[((size_t)(b * 64 + c)) * N_ + n];
        t.x = t.x * scs[c] + shs[c];
        t.y = t.y * scs[c] + shs[c];
        v[i] = t;
        ssa += t.x * t.x;  ssb += t.y * t.y;
    }
    ss4[qt][l * 2] = ssa;  ss4[qt][l * 2 + 1] = ssb;
    __syncthreads();
    float rna = 1.0f / (sqrtf(ss4[0][l*2]   + ss4[1][l*2]   + ss4[2][l*2]   + ss4[3][l*2])   + 1e-7f);
    float rnb = 1.0f / (sqrtf(ss4[0][l*2+1] + ss4[1][l*2+1] + ss4[2][l*2+1] + ss4[3][l*2+1]) + 1e-7f);
    #pragma unroll
    for (int i = 0; i < 16; i++) {
        int c = qt * 16 + i;
        *(float2*)&y[((size_t)(b * 64 + c)) * N_ + n] = make_float2(v[i].x * rna, v[i].y * rnb);
    }
}

// ---------------- K4: KV via bf16-split MMA (R13, unchanged) -----------------
__global__ __launch_bounds__(256) void kv_mma_kernel() {
    int chunk = blockIdx.x, b = blockIdx.y;
    int tid = threadIdx.x;
    int lane = tid & 31, w = tid >> 5;
    int ct = (w & 3) * 16;
    int cg = (w >> 2) * 32;

    __shared__ __align__(16) __nv_bfloat16 Kh[64 * ASTR];
    __shared__ __align__(16) __nv_bfloat16 Kl[64 * ASTR];
    __shared__ __align__(16) __nv_bfloat16 Vh[64 * ASTR];
    __shared__ __align__(16) __nv_bfloat16 Vl[64 * ASTR];
    __shared__ float vps[64][4];

    int q = lane >> 3, rr = lane & 7;
    unsigned aH, aL, bH0, bL0, bH1, bL1;
    {
        int arow = ct + (q & 1) * 8 + rr;
        int acol = (q >> 1) * 8;
        aH = su32(Kh) + arow * (ASTR * 2) + acol * 2;
        aL = su32(Kl) + arow * (ASTR * 2) + acol * 2;
        int brow = cg + (q >> 1) * 8 + rr;
        int bcol = (q & 1) * 8;
        bH0 = su32(Vh) + brow * (ASTR * 2) + bcol * 2;
        bL0 = su32(Vl) + brow * (ASTR * 2) + bcol * 2;
        bH1 = bH0 + 16 * (ASTR * 2);
        bL1 = bL0 + 16 * (ASTR * 2);
    }

    int cc = tid & 63, q4 = tid >> 6;
    int lrow = tid >> 4, lnn4 = (tid & 15) * 4;
    const float* kbase = &g_yk[((size_t)(b * 64 + lrow)) * N_ + chunk * 128 + lnn4];
    const float* vbase = &g_yv[((size_t)(b * 64 + lrow)) * N_ + chunk * 128 + lnn4];

    float acc[4][4] = {};
    float vp = 0.f;
    float4 kreg[4], vreg[4];
    #pragma unroll
    for (int i = 0; i < 4; i++) {
        kreg[i] = *(const float4*)(kbase + (size_t)(i * 16) * N_);
        vreg[i] = *(const float4*)(vbase + (size_t)(i * 16) * N_);
    }

    for (int t = 0; t < 2; t++) {
        #pragma unroll
        for (int i = 0; i < 4; i++) {
            int row = lrow + i * 16;
            uint2 hi, lo;
            split4(kreg[i], hi, lo);
            *(uint2*)&Kh[row * ASTR + lnn4] = hi;
            *(uint2*)&Kl[row * ASTR + lnn4] = lo;
            split4(vreg[i], hi, lo);
            *(uint2*)&Vh[row * ASTR + lnn4] = hi;
            *(uint2*)&Vl[row * ASTR + lnn4] = lo;
        }
        __syncthreads();

        if (t == 0) {
            #pragma unroll
            for (int i = 0; i < 4; i++) {
                kreg[i] = *(const float4*)(kbase + (size_t)(i * 16) * N_ + 64);
                vreg[i] = *(const float4*)(vbase + (size_t)(i * 16) * N_ + 64);
            }
        }

        #pragma unroll
        for (int ks = 0; ks < 4; ks++) {
            unsigned step = ks * 32;
            unsigned ah[4], al[4], bh[4], bl[4], bh2[4], bl2[4];
            LDSM_X4(ah, aH + step);
            LDSM_X4(al, aL + step);
            LDSM_X4(bh, bH0 + step);
            LDSM_X4(bl, bL0 + step);
            LDSM_X4(bh2, bH1 + step);
            LDSM_X4(bl2, bL1 + step);
            MMA_BF16(acc[0], ah, bh[0], bh[1]);
            MMA_BF16(acc[0], ah, bl[0], bl[1]);
            MMA_BF16(acc[0], al, bh[0], bh[1]);
            MMA_BF16(acc[1], ah, bh[2], bh[3]);
            MMA_BF16(acc[1], ah, bl[2], bl[3]);
            MMA_BF16(acc[1], al, bh[2], bh[3]);
            MMA_BF16(acc[2], ah, bh2[0], bh2[1]);
            MMA_BF16(acc[2], ah, bl2[0], bl2[1]);
            MMA_BF16(acc[2], al, bh2[0], bh2[1]);
            MMA_BF16(acc[3], ah, bh2[2], bh2[3]);
            MMA_BF16(acc[3], ah, bl2[2], bl2[3]);
            MMA_BF16(acc[3], al, bh2[2], bh2[3]);
        }
        #pragma unroll
        for (int i = 0; i < 16; i++) {
            int idx = cc * ASTR + q4 * 16 + i;
            vp += __bfloat162float(Vh[idx]) + __bfloat162float(Vl[idx]);
        }
        __syncthreads();
    }

    int r4 = lane >> 2, c2 = (lane & 3) * 2;
    int row0 = ct + r4, row1 = ct + r4 + 8;
    float* base = &g_kvpart[(((size_t)chunk * B_ + b)) * 4096];
    #pragma unroll
    for (int t = 0; t < 4; t++) {
        int col = cg + t * 8 + c2;
        *(float2*)&base[row0 * 64 + col] = make_float2(acc[t][0], acc[t][1]);
        *(float2*)&base[row1 * 64 + col] = make_float2(acc[t][2], acc[t][3]);
    }

    vps[cc][q4] = vp;
    __syncthreads();
    if (tid < 64)
        g_vsumpart[((size_t)chunk * B_ + b) * 64 + tid] =
            vps[tid][0] + vps[tid][1] + vps[tid][2] + vps[tid][3];
}

// ---------------- K5: M^T = (KV @ Ww^T)^T; obias (R13, unchanged) ------------
__global__ __launch_bounds__(256) void m_kernel(
    const float* __restrict__ Ww, const float* __restrict__ bw)
{
    int b = blockIdx.x;
    __shared__ float KVs[64][64];
    __shared__ float WwT[64][128];
    __shared__ float vs_s[64];
    int tid = threadIdx.x;

    if (tid < 64) {
        float S = 0.f;
        #pragma unroll
        for (int c2 = 0; c2 < KVCHUNKS; c2++)
            S += g_vsumpart[((size_t)c2 * B_ + b) * 64 + tid];
        vs_s[tid] = S;
    }
    for (int e = tid; e < 4096; e += 256) {
        float s = 0.f;
        #pragma unroll
        for (int c2 = 0; c2 < KVCHUNKS; c2++)
            s += g_kvpart[((size_t)c2 * B_ + b) * 4096 + e];
        KVs[e >> 6][e & 63] = s;
    }
    for (int e = tid; e < 8192; e += 256) {
        int cv = e >> 7, co = e & 127;
        WwT[cv][co] = Ww[co * CV + cv];
    }
    __syncthreads();

    int co = tid & 127;
    for (int ck = (tid >> 7); ck < 64; ck += 2) {
        float s = 0.f;
        #pragma unroll 8
        for (int cv = 0; cv < 64; cv++) s += KVs[ck][cv] * WwT[cv][co];
        g_M[((size_t)b * 128 + co) * 64 + ck] = s;
    }
    if (tid < 128) {
        float s = bw[tid];
        #pragma unroll 8
        for (int cv = 0; cv < 64; cv++) s += vs_s[cv] * WwT[cv][tid];
        g_obias[b * CO + tid] = s;
    }
}

// ---------------- K6: out via bf16-split MMA (R13, unchanged) ----------------
__global__ __launch_bounds__(256) void out_mma_kernel(float* __restrict__ out) {
    int b = blockIdx.y, n0 = blockIdx.x * 64, ch = blockIdx.z;
    int co0 = ch * 64;
    int tid = threadIdx.x;
    int lane = tid & 31, w = tid >> 5;
    int ct = (w & 3) * 16;
    int ng = (w >> 2) * 32;

    __shared__ __align__(16) __nv_bfloat16 Ah[64 * ASTR];
    __shared__ __align__(16) __nv_bfloat16 Al[64 * ASTR];
    __shared__ __align__(16) __nv_bfloat16 Bh[64 * BSTR];
    __shared__ __align__(16) __nv_bfloat16 Bl[64 * BSTR];

    int q = lane >> 3, rr = lane & 7;
    unsigned aOffH, aOffL, bOffH0, bOffL0, bOffH1, bOffL1;
    {
        int arow = ct + (q & 1) * 8 + rr;
        int acol = (q >> 1) * 8;
        aOffH = su32(Ah) + arow * (ASTR * 2) + acol * 2;
        aOffL = su32(Al) + arow * (ASTR * 2) + acol * 2;
        int brow = (q & 1) * 8 + rr;
        int bcol0 = ng + (q >> 1) * 8;
        int bcol1 = ng + 16 + (q >> 1) * 8;
        bOffH0 = su32(Bh) + brow * (BSTR * 2) + bcol0 * 2;
        bOffL0 = su32(Bl) + brow * (BSTR * 2) + bcol0 * 2;
        bOffH1 = su32(Bh) + brow * (BSTR * 2) + bcol1 * 2;
        bOffL1 = su32(Bl) + brow * (BSTR * 2) + bcol1 * 2;
    }

    #pragma unroll
    for (int i = 0; i < 4; i++) {
        int e = tid + i * 256;
        int row = e >> 4, ck4 = (e & 15) * 4;
        float4 f = *(const float4*)&g_M[((size_t)b * 128 + co0 + row) * 64 + ck4];
        uint2 hi, lo; split4(f, hi, lo);
        *(uint2*)&Ah[row * ASTR + ck4] = hi;
        *(uint2*)&Al[row * ASTR + ck4] = lo;
    }
    #pragma unroll
    for (int i = 0; i < 4; i++) {
        int e = tid + i * 256;
        int ck = e >> 4, nn4 = (e & 15) * 4;
        float4 f = *(const float4*)&g_yq[((size_t)(b * 64 + ck)) * N_ + n0 + nn4];
        uint2 hi, lo; split4(f, hi, lo);
        *(uint2*)&Bh[ck * BSTR + nn4] = hi;
        *(uint2*)&Bl[ck * BSTR + nn4] = lo;
    }
    __syncthreads();

    float acc[4][4] = {};
    #pragma unroll
    for (int ks = 0; ks < 4; ks++) {
        unsigned aStep = ks * 32;
        unsigned bStep = ks * 16 * (BSTR * 2);
        unsigned ah[4], al[4], bh[4], bl[4], bh2[4], bl2[4];
        LDSM_X4(ah, aOffH + aStep);
        LDSM_X4(al, aOffL + aStep);
        LDSM_X4T(bh, bOffH0 + bStep);
        LDSM_X4T(bl, bOffL0 + bStep);
        LDSM_X4T(bh2, bOffH1 + bStep);
        LDSM_X4T(bl2, bOffL1 + bStep);
        MMA_BF16(acc[0], ah, bh[0], bh[1]);
        MMA_BF16(acc[0], ah, bl[0], bl[1]);
        MMA_BF16(acc[0], al, bh[0], bh[1]);
        MMA_BF16(acc[1], ah, bh[2], bh[3]);
        MMA_BF16(acc[1], ah, bl[2], bl[3]);
        MMA_BF16(acc[1], al, bh[2], bh[3]);
        MMA_BF16(acc[2], ah, bh2[0], bh2[1]);
        MMA_BF16(acc[2], ah, bl2[0], bl2[1]);
        MMA_BF16(acc[2], al, bh2[0], bh2[1]);
        MMA_BF16(acc[3], ah, bh2[2], bh2[3]);
        MMA_BF16(acc[3], ah, bl2[2], bl2[3]);
        MMA_BF16(acc[3], al, bh2[2], bh2[3]);
    }

    int r4 = lane >> 2, c2 = (lane & 3) * 2;
    int row0 = co0 + ct + r4, row1 = row0 + 8;
    float b0v = g_obias[b * CO + row0], b1v = g_obias[b * CO + row1];
    #pragma unroll
    for (int t = 0; t < 4; t++) {
        int col = n0 + ng + t * 8 + c2;
        *(float2*)&out[((size_t)(b * CO + row0)) * N_ + col] =
            make_float2(acc[t][0] + b0v, acc[t][1] + b0v);
        *(float2*)&out[((size_t)(b * CO + row1)) * N_ + col] =
            make_float2(acc[t][2] + b1v, acc[t][3] + b1v);
    }
}

// ---------------- launch ----------------
extern "C" void kernel_launch(void* const* d_in, const int* in_sizes, int n_in,
                              void* d_out, int out_size) {
    const float* q     = (const float*)d_in[0];
    const float* k     = (const float*)d_in[1];
    const float* v     = (const float*)d_in[2];
    const float* Wk    = (const float*)d_in[3];
    const float* bk    = (const float*)d_in[4];
    const float* gamma = (const float*)d_in[5];
    const float* beta  = (const float*)d_in[6];
    const float* Wv    = (const float*)d_in[7];
    const float* bv    = (const float*)d_in[8];
    const float* Ww    = (const float*)d_in[9];
    const float* bw    = (const float*)d_in[10];
    float* out = (float*)d_out;

    prep_w_kernel<<<16, 256>>>(Wk, Wv);
    conv_mma_kernel<<<dim3(64, B_, 3), 256>>>(q, k, v, bk, bv);
    bn_stats_kernel<<<128, 256>>>(gamma, beta);
    norm_kernel<<<256, 512>>>();
    kv_mma_kernel<<<dim3(KVCHUNKS, B_), 256>>>();
    m_kernel<<<B_, 256>>>(Ww, bw);
    out_mma_kernel<<<dim3(64, B_, 2), 256>>>(out);
}

// round 16
// speedup vs baseline: 1.1677x; 1.0033x over previous
#include <cuda_runtime.h>
#include <cuda_bf16.h>
#include <math.h>

#define B_   8
#define CIN  128
#define CK   64
#define CV   64
#define CO   128
#define N_   4096
#define KVCHUNKS 32

// ---------------- scratch ----------------
__device__ float g_yq[B_ * CK * N_];
__device__ float g_yk[B_ * CK * N_];
__device__ float g_yv[B_ * CV * N_];
__device__ float g_scale[2 * CK];
__device__ float g_shift[2 * CK];
__device__ __nv_bfloat16 g_Wh[2 * 64 * CIN];
__device__ __nv_bfloat16 g_Wl[2 * 64 * CIN];
__device__ float g_vsumpart[KVCHUNKS * B_ * CV];
__device__ float g_kvpart[KVCHUNKS * B_ * CK * CV];
__device__ float g_M[B_ * CO * CK];
__device__ float g_obias[B_ * CO];

// ---------------- mma / ldmatrix helpers ----------------
__device__ __forceinline__ unsigned su32(const void* p) {
    return (unsigned)__cvta_generic_to_shared(p);
}
#define LDSM_X4(r, addr) \
    asm volatile("ldmatrix.sync.aligned.m8n8.x4.shared.b16 {%0,%1,%2,%3}, [%4];" \
        : "=r"((r)[0]), "=r"((r)[1]), "=r"((r)[2]), "=r"((r)[3]) : "r"(addr))
#define LDSM_X4T(r, addr) \
    asm volatile("ldmatrix.sync.aligned.m8n8.x4.trans.shared.b16 {%0,%1,%2,%3}, [%4];" \
        : "=r"((r)[0]), "=r"((r)[1]), "=r"((r)[2]), "=r"((r)[3]) : "r"(addr))
#define MMA_BF16(d, a, b0, b1) \
    asm volatile("mma.sync.aligned.m16n8k16.row.col.f32.bf16.bf16.f32 " \
        "{%0,%1,%2,%3}, {%4,%5,%6,%7}, {%8,%9}, {%0,%1,%2,%3};" \
        : "+f"((d)[0]), "+f"((d)[1]), "+f"((d)[2]), "+f"((d)[3]) \
        : "r"((a)[0]), "r"((a)[1]), "r"((a)[2]), "r"((a)[3]), "r"(b0), "r"(b1))

__device__ __forceinline__ unsigned packbf(__nv_bfloat16 lo, __nv_bfloat16 hi) {
    return ((unsigned)__bfloat16_as_ushort(hi) << 16) | __bfloat16_as_ushort(lo);
}
__device__ __forceinline__ void split4(float4 f, uint2 &hi, uint2 &lo) {
    __nv_bfloat16 hx = __float2bfloat16(f.x), hy = __float2bfloat16(f.y);
    __nv_bfloat16 hz = __float2bfloat16(f.z), hw = __float2bfloat16(f.w);
    __nv_bfloat16 lx = __float2bfloat16(f.x - __bfloat162float(hx));
    __nv_bfloat16 ly = __float2bfloat16(f.y - __bfloat162float(hy));
    __nv_bfloat16 lz = __float2bfloat16(f.z - __bfloat162float(hz));
    __nv_bfloat16 lw = __float2bfloat16(f.w - __bfloat162float(hw));
    hi.x = packbf(hx, hy); hi.y = packbf(hz, hw);
    lo.x = packbf(lx, ly); lo.y = packbf(lz, lw);
}

#define ASTR 72
#define BSTR 72
#define BSTR2 136   // 128-wide B tile row stride (+8 pad)

// conv dynamic smem: Ah/Al 64*72 + Bh/Bl 64*136 bf16
#define CONV_SMEM ((2 * 64 * ASTR + 2 * 64 * BSTR2) * 2)

// ---------------- K0: pre-split weights ----------------
__global__ void prep_w_kernel(const float* __restrict__ Wk, const float* __restrict__ Wv) {
    int e = blockIdx.x * 256 + threadIdx.x;
    int wsel = e >> 11;
    int r4 = (e & 2047) * 4;
    float4 f = *(const float4*)((wsel ? Wv : Wk) + r4);
    uint2 hi, lo; split4(f, hi, lo);
    *(uint2*)&g_Wh[wsel * 8192 + r4] = hi;
    *(uint2*)&g_Wl[wsel * 8192 + r4] = lo;
}

// ---------------- K1: conv via bf16-split MMA, 64co x 128n tile --------------
// grid (32, B_, 3), 256 threads, dynamic smem 53.2 KB.
__global__ __launch_bounds__(256) void conv_mma_kernel(
    const float* __restrict__ xq, const float* __restrict__ xk,
    const float* __restrict__ xv,
    const float* __restrict__ bk, const float* __restrict__ bv)
{
    extern __shared__ char smem_raw[];
    __nv_bfloat16* Ah = (__nv_bfloat16*)smem_raw;
    __nv_bfloat16* Al = Ah + 64 * ASTR;
    __nv_bfloat16* Bh = Al + 64 * ASTR;
    __nv_bfloat16* Bl = Bh + 64 * BSTR2;

    int which = blockIdx.z;
    const float* x    = (which == 0) ? xq : (which == 1) ? xk : xv;
    const float* bias = (which == 2) ? bv : bk;
    int wsel = (which == 2) ? 1 : 0;
    const __nv_bfloat16* WhP = &g_Wh[wsel * 8192];
    const __nv_bfloat16* WlP = &g_Wl[wsel * 8192];
    float* y          = (which == 0) ? g_yq : (which == 1) ? g_yk : g_yv;

    int bb = blockIdx.y;
    int n0 = blockIdx.x * 128;
    int tid = threadIdx.x;
    int lane = tid & 31, w = tid >> 5;
    int ct = (w & 3) * 16;            // co tile base
    int ng = (w >> 2) * 64;           // n half base (0 or 64)

    int q = lane >> 3, rr = lane & 7;
    unsigned aOffH, aOffL, bOffH[4], bOffL[4];
    {
        int arow = ct + (q & 1) * 8 + rr;
        int acol = (q >> 1) * 8;
        aOffH = su32(Ah) + arow * (ASTR * 2) + acol * 2;
        aOffL = su32(Al) + arow * (ASTR * 2) + acol * 2;
        int brow = (q & 1) * 8 + rr;
        #pragma unroll
        for (int j = 0; j < 4; j++) {
            int bcol = ng + j * 16 + (q >> 1) * 8;
            bOffH[j] = su32(Bh) + brow * (BSTR2 * 2) + bcol * 2;
            bOffL[j] = su32(Bl) + brow * (BSTR2 * 2) + bcol * 2;
        }
    }

    // x staging coords: 2048 float4/stage, 8 per thread
    int wrow = tid >> 3, wc8 = (tid & 7) * 8;    // W copy coords

    float acc[8][4] = {};
    float4 xreg[8];
    #pragma unroll
    for (int i = 0; i < 8; i++) {
        int e = tid + i * 256;
        int row = e >> 5, col4 = (e & 31) * 4;
        xreg[i] = *(const float4*)&x[((size_t)(bb * CIN + row)) * N_ + n0 + col4];
    }

    for (int s = 0; s < 2; s++) {
        #pragma unroll
        for (int i = 0; i < 2; i++) {
            int row = wrow + i * 32;
            *(uint4*)&Ah[row * ASTR + wc8] = *(const uint4*)&WhP[row * CIN + s * 64 + wc8];
            *(uint4*)&Al[row * ASTR + wc8] = *(const uint4*)&WlP[row * CIN + s * 64 + wc8];
        }
        #pragma unroll
        for (int i = 0; i < 8; i++) {
            int e = tid + i * 256;
            int row = e >> 5, col4 = (e & 31) * 4;
            uint2 hi, lo; split4(xreg[i], hi, lo);
            *(uint2*)&Bh[row * BSTR2 + col4] = hi;
            *(uint2*)&Bl[row * BSTR2 + col4] = lo;
        }
        __syncthreads();

        if (s == 0) {
            #pragma unroll
            for (int i = 0; i < 8; i++) {
                int e = tid + i * 256;
                int row = e >> 5, col4 = (e & 31) * 4;
                xreg[i] = *(const float4*)&x[((size_t)(bb * CIN + 64 + row)) * N_ + n0 + col4];
            }
        }

        #pragma unroll
        for (int ks = 0; ks < 4; ks++) {
            unsigned aStep = ks * 32;
            unsigned bStep = ks * 16 * (BSTR2 * 2);
            unsigned ah[4], al[4];
            LDSM_X4(ah, aOffH + aStep);
            LDSM_X4(al, aOffL + aStep);
            #pragma unroll
            for (int j = 0; j < 4; j++) {
                unsigned bh[4], bl[4];
                LDSM_X4T(bh, bOffH[j] + bStep);
                LDSM_X4T(bl, bOffL[j] + bStep);
                MMA_BF16(acc[2 * j],     ah, bh[0], bh[1]);
                MMA_BF16(acc[2 * j],     ah, bl[0], bl[1]);
                MMA_BF16(acc[2 * j],     al, bh[0], bh[1]);
                MMA_BF16(acc[2 * j + 1], ah, bh[2], bh[3]);
                MMA_BF16(acc[2 * j + 1], ah, bl[2], bl[3]);
                MMA_BF16(acc[2 * j + 1], al, bh[2], bh[3]);
            }
        }
        __syncthreads();
    }

    int r4 = lane >> 2, c2 = (lane & 3) * 2;
    int row0 = ct + r4, row1 = ct + r4 + 8;
    float b0v = bias[row0], b1v = bias[row1];
    #pragma unroll
    for (int t = 0; t < 8; t++) {
        int col = n0 + ng + t * 8 + c2;
        *(float2*)&y[((size_t)(bb * 64 + row0)) * N_ + col] =
            make_float2(acc[t][0] + b0v, acc[t][1] + b0v);
        *(float2*)&y[((size_t)(bb * 64 + row1)) * N_ + col] =
            make_float2(acc[t][2] + b1v, acc[t][3] + b1v);
    }
}

// ---------------- K2: BN batch stats (unchanged) ----------------
__global__ __launch_bounds__(256) void bn_stats_kernel(
    const float* __restrict__ gamma, const float* __restrict__ beta)
{
    int c = blockIdx.x & 63;
    int which = blockIdx.x >> 6;
    const float* y = which ? g_yk : g_yq;
    int tid = threadIdx.x;

    float s = 0.f, ss = 0.f;
    #pragma unroll
    for (int b = 0; b < B_; b++) {
        const float4* row = (const float4*)(y + ((size_t)(b * 64 + c)) * N_);
        #pragma unroll
        for (int i = 0; i < 4; i++) {
            float4 f = row[tid + i * 256];
            s  += f.x + f.y + f.z + f.w;
            ss += f.x * f.x + f.y * f.y + f.z * f.z + f.w * f.w;
        }
    }
    #pragma unroll
    for (int o = 16; o; o >>= 1) {
        s  += __shfl_down_sync(0xffffffffu, s, o);
        ss += __shfl_down_sync(0xffffffffu, ss, o);
    }
    __shared__ float rs[8], rss[8];
    int wid = tid >> 5, lane = tid & 31;
    if (lane == 0) { rs[wid] = s; rss[wid] = ss; }
    __syncthreads();
    if (tid == 0) {
        float S = 0.f, SS = 0.f;
        #pragma unroll
        for (int i = 0; i < 8; i++) { S += rs[i]; SS += rss[i]; }
        const float inv = 1.0f / 32768.0f;
        float mean = S * inv;
        float var  = SS * inv - mean * mean;
        float sc = gamma[c] * rsqrtf(var + 1e-5f);
        g_scale[blockIdx.x] = sc;
        g_shift[blockIdx.x] = beta[c] - mean * sc;
    }
}

// ---------------- K3: apply BN + L2-normalize (unchanged) --------------------
__global__ __launch_bounds__(512) void norm_kernel() {
    int blk = blockIdx.x;
    int which = blk >> 7;
    int r = blk & 127;
    int b = r >> 4;
    int n0 = (r & 15) * 256;
    float* y = which ? g_yk : g_yq;
    int tid = threadIdx.x;
    int qt = tid >> 7;
    int l = tid & 127;
    int n = n0 + l * 2;

    __shared__ float scs[64], shs[64];
    __shared__ float ss4[4][256];
    if (tid < 64) {
        scs[tid] = g_scale[which * 64 + tid];
        shs[tid] = g_shift[which * 64 + tid];
    }
    __syncthreads();

    float2 v[16];
    float ssa = 0.f, ssb = 0.f;
    #pragma unroll
    for (int i = 0; i < 16; i++) {
        int c = qt * 16 + i;
        float2 t = *(const float2*)&y[((size_t)(b * 64 + c)) * N_ + n];
        t.x = t.x * scs[c] + shs[c];
        t.y = t.y * scs[c] + shs[c];
        v[i] = t;
        ssa += t.x * t.x;  ssb += t.y * t.y;
    }
    ss4[qt][l * 2] = ssa;  ss4[qt][l * 2 + 1] = ssb;
    __syncthreads();
    float rna = 1.0f / (sqrtf(ss4[0][l*2]   + ss4[1][l*2]   + ss4[2][l*2]   + ss4[3][l*2])   + 1e-7f);
    float rnb = 1.0f / (sqrtf(ss4[0][l*2+1] + ss4[1][l*2+1] + ss4[2][l*2+1] + ss4[3][l*2+1]) + 1e-7f);
    #pragma unroll
    for (int i = 0; i < 16; i++) {
        int c = qt * 16 + i;
        *(float2*)&y[((size_t)(b * 64 + c)) * N_ + n] = make_float2(v[i].x * rna, v[i].y * rnb);
    }
}

// ---------------- K4: KV via bf16-split MMA (unchanged) ----------------------
__global__ __launch_bounds__(256) void kv_mma_kernel() {
    int chunk = blockIdx.x, b = blockIdx.y;
    int tid = threadIdx.x;
    int lane = tid & 31, w = tid >> 5;
    int ct = (w & 3) * 16;
    int cg = (w >> 2) * 32;

    __shared__ __align__(16) __nv_bfloat16 Kh[64 * ASTR];
    __shared__ __align__(16) __nv_bfloat16 Kl[64 * ASTR];
    __shared__ __align__(16) __nv_bfloat16 Vh[64 * ASTR];
    __shared__ __align__(16) __nv_bfloat16 Vl[64 * ASTR];
    __shared__ float vps[64][4];

    int q = lane >> 3, rr = lane & 7;
    unsigned aH, aL, bH0, bL0, bH1, bL1;
    {
        int arow = ct + (q & 1) * 8 + rr;
        int acol = (q >> 1) * 8;
        aH = su32(Kh) + arow * (ASTR * 2) + acol * 2;
        aL = su32(Kl) + arow * (ASTR * 2) + acol * 2;
        int brow = cg + (q >> 1) * 8 + rr;
        int bcol = (q & 1) * 8;
        bH0 = su32(Vh) + brow * (ASTR * 2) + bcol * 2;
        bL0 = su32(Vl) + brow * (ASTR * 2) + bcol * 2;
        bH1 = bH0 + 16 * (ASTR * 2);
        bL1 = bL0 + 16 * (ASTR * 2);
    }

    int cc = tid & 63, q4 = tid >> 6;
    int lrow = tid >> 4, lnn4 = (tid & 15) * 4;
    const float* kbase = &g_yk[((size_t)(b * 64 + lrow)) * N_ + chunk * 128 + lnn4];
    const float* vbase = &g_yv[((size_t)(b * 64 + lrow)) * N_ + chunk * 128 + lnn4];

    float acc[4][4] = {};
    float vp = 0.f;
    float4 kreg[4], vreg[4];
    #pragma unroll
    for (int i = 0; i < 4; i++) {
        kreg[i] = *(const float4*)(kbase + (size_t)(i * 16) * N_);
        vreg[i] = *(const float4*)(vbase + (size_t)(i * 16) * N_);
    }

    for (int t = 0; t < 2; t++) {
        #pragma unroll
        for (int i = 0; i < 4; i++) {
            int row = lrow + i * 16;
            uint2 hi, lo;
            split4(kreg[i], hi, lo);
            *(uint2*)&Kh[row * ASTR + lnn4] = hi;
            *(uint2*)&Kl[row * ASTR + lnn4] = lo;
            split4(vreg[i], hi, lo);
            *(uint2*)&Vh[row * ASTR + lnn4] = hi;
            *(uint2*)&Vl[row * ASTR + lnn4] = lo;
        }
        __syncthreads();

        if (t == 0) {
            #pragma unroll
            for (int i = 0; i < 4; i++) {
                kreg[i] = *(const float4*)(kbase + (size_t)(i * 16) * N_ + 64);
                vreg[i] = *(const float4*)(vbase + (size_t)(i * 16) * N_ + 64);
            }
        }

        #pragma unroll
        for (int ks = 0; ks < 4; ks++) {
            unsigned step = ks * 32;
            unsigned ah[4], al[4], bh[4], bl[4], bh2[4], bl2[4];
            LDSM_X4(ah, aH + step);
            LDSM_X4(al, aL + step);
            LDSM_X4(bh, bH0 + step);
            LDSM_X4(bl, bL0 + step);
            LDSM_X4(bh2, bH1 + step);
            LDSM_X4(bl2, bL1 + step);
            MMA_BF16(acc[0], ah, bh[0], bh[1]);
            MMA_BF16(acc[0], ah, bl[0], bl[1]);
            MMA_BF16(acc[0], al, bh[0], bh[1]);
            MMA_BF16(acc[1], ah, bh[2], bh[3]);
            MMA_BF16(acc[1], ah, bl[2], bl[3]);
            MMA_BF16(acc[1], al, bh[2], bh[3]);
            MMA_BF16(acc[2], ah, bh2[0], bh2[1]);
            MMA_BF16(acc[2], ah, bl2[0], bl2[1]);
            MMA_BF16(acc[2], al, bh2[0], bh2[1]);
            MMA_BF16(acc[3], ah, bh2[2], bh2[3]);
            MMA_BF16(acc[3], ah, bl2[2], bl2[3]);
            MMA_BF16(acc[3], al, bh2[2], bh2[3]);
        }
        #pragma unroll
        for (int i = 0; i < 16; i++) {
            int idx = cc * ASTR + q4 * 16 + i;
            vp += __bfloat162float(Vh[idx]) + __bfloat162float(Vl[idx]);
        }
        __syncthreads();
    }

    int r4 = lane >> 2, c2 = (lane & 3) * 2;
    int row0 = ct + r4, row1 = ct + r4 + 8;
    float* base = &g_kvpart[(((size_t)chunk * B_ + b)) * 4096];
    #pragma unroll
    for (int t = 0; t < 4; t++) {
        int col = cg + t * 8 + c2;
        *(float2*)&base[row0 * 64 + col] = make_float2(acc[t][0], acc[t][1]);
        *(float2*)&base[row1 * 64 + col] = make_float2(acc[t][2], acc[t][3]);
    }

    vps[cc][q4] = vp;
    __syncthreads();
    if (tid < 64)
        g_vsumpart[((size_t)chunk * B_ + b) * 64 + tid] =
            vps[tid][0] + vps[tid][1] + vps[tid][2] + vps[tid][3];
}

// ---------------- K5: M^T = (KV @ Ww^T)^T; obias (unchanged) -----------------
__global__ __launch_bounds__(256) void m_kernel(
    const float* __restrict__ Ww, const float* __restrict__ bw)
{
    int b = blockIdx.x;
    __shared__ float KVs[64][64];
    __shared__ float WwT[64][128];
    __shared__ float vs_s[64];
    int tid = threadIdx.x;

    if (tid < 64) {
        float S = 0.f;
        #pragma unroll
        for (int c2 = 0; c2 < KVCHUNKS; c2++)
            S += g_vsumpart[((size_t)c2 * B_ + b) * 64 + tid];
        vs_s[tid] = S;
    }
    for (int e = tid; e < 4096; e += 256) {
        float s = 0.f;
        #pragma unroll
        for (int c2 = 0; c2 < KVCHUNKS; c2++)
            s += g_kvpart[((size_t)c2 * B_ + b) * 4096 + e];
        KVs[e >> 6][e & 63] = s;
    }
    for (int e = tid; e < 8192; e += 256) {
        int cv = e >> 7, co = e & 127;
        WwT[cv][co] = Ww[co * CV + cv];
    }
    __syncthreads();

    int co = tid & 127;
    for (int ck = (tid >> 7); ck < 64; ck += 2) {
        float s = 0.f;
        #pragma unroll 8
        for (int cv = 0; cv < 64; cv++) s += KVs[ck][cv] * WwT[cv][co];
        g_M[((size_t)b * 128 + co) * 64 + ck] = s;
    }
    if (tid < 128) {
        float s = bw[tid];
        #pragma unroll 8
        for (int cv = 0; cv < 64; cv++) s += vs_s[cv] * WwT[cv][tid];
        g_obias[b * CO + tid] = s;
    }
}

// ---------------- K6: out via bf16-split MMA (unchanged) ---------------------
__global__ __launch_bounds__(256) void out_mma_kernel(float* __restrict__ out) {
    int b = blockIdx.y, n0 = blockIdx.x * 64, ch = blockIdx.z;
    int co0 = ch * 64;
    int tid = threadIdx.x;
    int lane = tid & 31, w = tid >> 5;
    int ct = (w & 3) * 16;
    int ng = (w >> 2) * 32;

    __shared__ __align__(16) __nv_bfloat16 Ah[64 * ASTR];
    __shared__ __align__(16) __nv_bfloat16 Al[64 * ASTR];
    __shared__ __align__(16) __nv_bfloat16 Bh[64 * BSTR];
    __shared__ __align__(16) __nv_bfloat16 Bl[64 * BSTR];

    int q = lane >> 3, rr = lane & 7;
    unsigned aOffH, aOffL, bOffH0, bOffL0, bOffH1, bOffL1;
    {
        int arow = ct + (q & 1) * 8 + rr;
        int acol = (q >> 1) * 8;
        aOffH = su32(Ah) + arow * (ASTR * 2) + acol * 2;
        aOffL = su32(Al) + arow * (ASTR * 2) + acol * 2;
        int brow = (q & 1) * 8 + rr;
        int bcol0 = ng + (q >> 1) * 8;
        int bcol1 = ng + 16 + (q >> 1) * 8;
        bOffH0 = su32(Bh) + brow * (BSTR * 2) + bcol0 * 2;
        bOffL0 = su32(Bl) + brow * (BSTR * 2) + bcol0 * 2;
        bOffH1 = su32(Bh) + brow * (BSTR * 2) + bcol1 * 2;
        bOffL1 = su32(Bl) + brow * (BSTR * 2) + bcol1 * 2;
    }

    #pragma unroll
    for (int i = 0; i < 4; i++) {
        int e = tid + i * 256;
        int row = e >> 4, ck4 = (e & 15) * 4;
        float4 f = *(const float4*)&g_M[((size_t)b * 128 + co0 + row) * 64 + ck4];
        uint2 hi, lo; split4(f, hi, lo);
        *(uint2*)&Ah[row * ASTR + ck4] = hi;
        *(uint2*)&Al[row * ASTR + ck4] = lo;
    }
    #pragma unroll
    for (int i = 0; i < 4; i++) {
        int e = tid + i * 256;
        int ck = e >> 4, nn4 = (e & 15) * 4;
        float4 f = *(const float4*)&g_yq[((size_t)(b * 64 + ck)) * N_ + n0 + nn4];
        uint2 hi, lo; split4(f, hi, lo);
        *(uint2*)&Bh[ck * BSTR + nn4] = hi;
        *(uint2*)&Bl[ck * BSTR + nn4] = lo;
    }
    __syncthreads();

    float acc[4][4] = {};
    #pragma unroll
    for (int ks = 0; ks < 4; ks++) {
        unsigned aStep = ks * 32;
        unsigned bStep = ks * 16 * (BSTR * 2);
        unsigned ah[4], al[4], bh[4], bl[4], bh2[4], bl2[4];
        LDSM_X4(ah, aOffH + aStep);
        LDSM_X4(al, aOffL + aStep);
        LDSM_X4T(bh, bOffH0 + bStep);
        LDSM_X4T(bl, bOffL0 + bStep);
        LDSM_X4T(bh2, bOffH1 + bStep);
        LDSM_X4T(bl2, bOffL1 + bStep);
        MMA_BF16(acc[0], ah, bh[0], bh[1]);
        MMA_BF16(acc[0], ah, bl[0], bl[1]);
        MMA_BF16(acc[0], al, bh[0], bh[1]);
        MMA_BF16(acc[1], ah, bh[2], bh[3]);
        MMA_BF16(acc[1], ah, bl[2], bl[3]);
        MMA_BF16(acc[1], al, bh[2], bh[3]);
        MMA_BF16(acc[2], ah, bh2[0], bh2[1]);
        MMA_BF16(acc[2], ah, bl2[0], bl2[1]);
        MMA_BF16(acc[2], al, bh2[0], bh2[1]);
        MMA_BF16(acc[3], ah, bh2[2], bh2[3]);
        MMA_BF16(acc[3], ah, bl2[2], bl2[3]);
        MMA_BF16(acc[3], al, bh2[2], bh2[3]);
    }

    int r4 = lane >> 2, c2 = (lane & 3) * 2;
    int row0 = co0 + ct + r4, row1 = row0 + 8;
    float b0v = g_obias[b * CO + row0], b1v = g_obias[b * CO + row1];
    #pragma unroll
    for (int t = 0; t < 4; t++) {
        int col = n0 + ng + t * 8 + c2;
        *(float2*)&out[((size_t)(b * CO + row0)) * N_ + col] =
            make_float2(acc[t][0] + b0v, acc[t][1] + b0v);
        *(float2*)&out[((size_t)(b * CO + row1)) * N_ + col] =
            make_float2(acc[t][2] + b1v, acc[t][3] + b1v);
    }
}

// ---------------- launch ----------------
extern "C" void kernel_launch(void* const* d_in, const int* in_sizes, int n_in,
                              void* d_out, int out_size) {
    const float* q     = (const float*)d_in[0];
    const float* k     = (const float*)d_in[1];
    const float* v     = (const float*)d_in[2];
    const float* Wk    = (const float*)d_in[3];
    const float* bk    = (const float*)d_in[4];
    const float* gamma = (const float*)d_in[5];
    const float* beta  = (const float*)d_in[6];
    const float* Wv    = (const float*)d_in[7];
    const float* bv    = (const float*)d_in[8];
    const float* Ww    = (const float*)d_in[9];
    const float* bw    = (const float*)d_in[10];
    float* out = (float*)d_out;

    cudaFuncSetAttribute(conv_mma_kernel,
                         cudaFuncAttributeMaxDynamicSharedMemorySize, CONV_SMEM);

    prep_w_kernel<<<16, 256>>>(Wk, Wv);
    conv_mma_kernel<<<dim3(32, B_, 3), 256, CONV_SMEM>>>(q, k, v, bk, bv);
    bn_stats_kernel<<<128, 256>>>(gamma, beta);
    norm_kernel<<<256, 512>>>();
    kv_mma_kernel<<<dim3(KVCHUNKS, B_), 256>>>();
    m_kernel<<<B_, 256>>>(Ww, bw);
    out_mma_kernel<<<dim3(64, B_, 2), 256>>>(out);
}